// round 5
// baseline (speedup 1.0000x reference)
#include <cuda_runtime.h>

// SpecNorm: x [B=16, T=2000, F=481, 2] fp32.
//   s_t = 0.9*s_{t-1} + 0.1*|x_t|  (per (b,f) chain over t)
//   out = x * rsqrt(s_t + 1e-12)
//
// Strategy: chunk T into C=8 chunks of S=250. Each chunk warms up its EMA
// state over the preceding W=160 steps starting from s=0 (alpha^160 ~ 5e-8
// relative error, far below the 1e-3 tolerance). Chunk 0 starts at t=0 with
// the exact linear-ramp init. This gives 61,568 independent threads (1924
// warps) instead of 7696, enough MLP to approach the HBM roofline.
// Threads map f-fastest so a warp loads 256 contiguous bytes per t-step.

static constexpr int  B_ = 16;
static constexpr int  T_ = 2000;
static constexpr int  F_ = 481;
static constexpr int  S_ = 250;       // output chunk length
static constexpr int  C_ = T_ / S_;   // 8 chunks
static constexpr int  W_ = 160;       // lookback warm-up steps (alpha^160 ~ 5e-8)

static constexpr float ALPHA   = 0.9f;
static constexpr float ONE_MA  = 0.1f;   // float(1.0 - 0.9)
static constexpr float EPS_    = 1e-12f;

__global__ __launch_bounds__(256)
void specnorm_kernel(const float2* __restrict__ x, float2* __restrict__ out) {
    int g = blockIdx.x * blockDim.x + threadIdx.x;
    constexpr int BF = B_ * F_;
    if (g >= BF * C_) return;

    int c = g / BF;
    int r = g - c * BF;
    int b = r / F_;
    int f = r - b * F_;

    int t_out = c * S_;          // first output timestep for this chunk
    int t0    = t_out - W_;      // warm-up start

    float s;
    if (t0 <= 0) {
        // chunk 0: exact initial state (linear ramp over F)
        t0 = 0;
        const float step = (0.0001f - 0.001f) / (float)(F_ - 1);
        s = 0.001f + (float)f * step;
    } else {
        s = 0.0f;                // cold start; warm-up converges it
    }

    // linear index in float2 units: (b*T + t)*F + f   (max ~15.4M, fits int)
    int idx = (b * T_ + t0) * F_ + f;
    int nwarm = t_out - t0;      // 0 or W_

    // Warm-up: EMA only, no output. Loads are independent of the s chain,
    // so unrolling lets the compiler batch them for MLP.
    #pragma unroll 8
    for (int i = 0; i < nwarm; ++i, idx += F_) {
        float2 v = x[idx];
        float a = sqrtf(fmaf(v.x, v.x, v.y * v.y));
        s = fmaf(ALPHA, s, ONE_MA * a);
    }

    // Output region.
    #pragma unroll 5
    for (int i = 0; i < S_; ++i, idx += F_) {
        float2 v = x[idx];
        float a = sqrtf(fmaf(v.x, v.x, v.y * v.y));
        s = fmaf(ALPHA, s, ONE_MA * a);
        float inv = rsqrtf(s + EPS_);
        float2 o;
        o.x = v.x * inv;
        o.y = v.y * inv;
        out[idx] = o;
    }
}

extern "C" void kernel_launch(void* const* d_in, const int* in_sizes, int n_in,
                              void* d_out, int out_size) {
    const float2* x = (const float2*)d_in[0];
    float2*     out = (float2*)d_out;
    int n = B_ * F_ * C_;                 // 61,568 threads
    int threads = 256;
    int blocks = (n + threads - 1) / threads;
    specnorm_kernel<<<blocks, threads>>>(x, out);
}

// round 6
// speedup vs baseline: 1.0015x; 1.0015x over previous
#include <cuda_runtime.h>

// SpecNorm: x [B=16, T=2000, F=481, 2] fp32.
//   s_t = 0.9*s_{t-1} + 0.1*|x_t|  (per (b,f) chain over t)
//   out = x * rsqrt(s_t + 1e-12)
//
// Strategy: chunk T into C=8 chunks of S=250. Each chunk warms up its EMA
// state over the preceding W=160 steps starting from s=0 (alpha^160 ~ 5e-8
// relative error, far below the 1e-3 tolerance). Chunk 0 starts at t=0 with
// the exact linear-ramp init. This gives 61,568 independent threads (1924
// warps) instead of 7696, enough MLP to approach the HBM roofline.
// Threads map f-fastest so a warp loads 256 contiguous bytes per t-step.

static constexpr int  B_ = 16;
static constexpr int  T_ = 2000;
static constexpr int  F_ = 481;
static constexpr int  S_ = 250;       // output chunk length
static constexpr int  C_ = T_ / S_;   // 8 chunks
static constexpr int  W_ = 160;       // lookback warm-up steps (alpha^160 ~ 5e-8)

static constexpr float ALPHA   = 0.9f;
static constexpr float ONE_MA  = 0.1f;   // float(1.0 - 0.9)
static constexpr float EPS_    = 1e-12f;

__global__ __launch_bounds__(256)
void specnorm_kernel(const float2* __restrict__ x, float2* __restrict__ out) {
    int g = blockIdx.x * blockDim.x + threadIdx.x;
    constexpr int BF = B_ * F_;
    if (g >= BF * C_) return;

    int c = g / BF;
    int r = g - c * BF;
    int b = r / F_;
    int f = r - b * F_;

    int t_out = c * S_;          // first output timestep for this chunk
    int t0    = t_out - W_;      // warm-up start

    float s;
    if (t0 <= 0) {
        // chunk 0: exact initial state (linear ramp over F)
        t0 = 0;
        const float step = (0.0001f - 0.001f) / (float)(F_ - 1);
        s = 0.001f + (float)f * step;
    } else {
        s = 0.0f;                // cold start; warm-up converges it
    }

    // linear index in float2 units: (b*T + t)*F + f   (max ~15.4M, fits int)
    int idx = (b * T_ + t0) * F_ + f;
    int nwarm = t_out - t0;      // 0 or W_

    // Warm-up: EMA only, no output. Loads are independent of the s chain,
    // so unrolling lets the compiler batch them for MLP.
    #pragma unroll 8
    for (int i = 0; i < nwarm; ++i, idx += F_) {
        float2 v = x[idx];
        float a = sqrtf(fmaf(v.x, v.x, v.y * v.y));
        s = fmaf(ALPHA, s, ONE_MA * a);
    }

    // Output region.
    #pragma unroll 5
    for (int i = 0; i < S_; ++i, idx += F_) {
        float2 v = x[idx];
        float a = sqrtf(fmaf(v.x, v.x, v.y * v.y));
        s = fmaf(ALPHA, s, ONE_MA * a);
        float inv = rsqrtf(s + EPS_);
        float2 o;
        o.x = v.x * inv;
        o.y = v.y * inv;
        out[idx] = o;
    }
}

extern "C" void kernel_launch(void* const* d_in, const int* in_sizes, int n_in,
                              void* d_out, int out_size) {
    const float2* x = (const float2*)d_in[0];
    float2*     out = (float2*)d_out;
    int n = B_ * F_ * C_;                 // 61,568 threads
    int threads = 256;
    int blocks = (n + threads - 1) / threads;
    specnorm_kernel<<<blocks, threads>>>(x, out);
}

// round 7
// speedup vs baseline: 3.7257x; 3.7201x over previous
#include <cuda_runtime.h>

// SpecNorm: x [B=16, T=2000, F=481, 2] fp32.
//   s_t = 0.9*s_{t-1} + 0.1*|x_t|;  out = x * rsqrt(s_t + 1e-12)
//
// R6 analysis: 241 blocks / MLP~1 per thread -> latency-bound at 16% DRAM.
// This version: C=20 chunks of S=100 (W=90 lookback warm-up, alpha^90~7.6e-5
// << 1e-3 tol) -> 153,920 threads (~26 warps/SM), and a two-phase unrolled
// body (load U=10 float2 into a register array, THEN compute) to force
// 10 outstanding loads per thread. Warp still loads 256B contiguous per step.

static constexpr int  B_ = 16;
static constexpr int  T_ = 2000;
static constexpr int  F_ = 481;
static constexpr int  S_ = 100;       // output chunk length
static constexpr int  C_ = T_ / S_;   // 20 chunks
static constexpr int  W_ = 90;        // warm-up steps (alpha^90 ~ 7.6e-5)
static constexpr int  U_ = 10;        // forced-MLP batch size

static constexpr float ALPHA  = 0.9f;
static constexpr float ONE_MA = 0.1f;
static constexpr float EPS_   = 1e-12f;

__global__ __launch_bounds__(256)
void specnorm_kernel(const float2* __restrict__ x, float2* __restrict__ out) {
    int g = blockIdx.x * blockDim.x + threadIdx.x;
    constexpr int BF = B_ * F_;
    if (g >= BF * C_) return;

    int c = g / BF;
    int r = g - c * BF;
    int b = r / F_;
    int f = r - b * F_;

    int t_out = c * S_;
    float s;
    int idx;                           // float2-unit linear index

    if (c == 0) {
        // exact initial state: linear ramp over F
        const float step = (0.0001f - 0.001f) / (float)(F_ - 1);
        s = 0.001f + (float)f * step;
        idx = b * (T_ * F_) + f;
    } else {
        // cold-start warm-up over the previous W_ steps
        s = 0.0f;
        idx = (b * T_ + (t_out - W_)) * F_ + f;
        #pragma unroll 1
        for (int i = 0; i < W_ / U_; ++i) {
            float2 v[U_];
            #pragma unroll
            for (int j = 0; j < U_; ++j) v[j] = x[idx + j * F_];   // batch loads
            float a[U_];
            #pragma unroll
            for (int j = 0; j < U_; ++j)
                a[j] = sqrtf(fmaf(v[j].x, v[j].x, v[j].y * v[j].y));
            #pragma unroll
            for (int j = 0; j < U_; ++j)
                s = fmaf(ALPHA, s, ONE_MA * a[j]);
            idx += U_ * F_;
        }
    }

    // Output region: same two-phase batching.
    #pragma unroll 1
    for (int i = 0; i < S_ / U_; ++i) {
        float2 v[U_];
        #pragma unroll
        for (int j = 0; j < U_; ++j) v[j] = x[idx + j * F_];       // batch loads
        float a[U_];
        #pragma unroll
        for (int j = 0; j < U_; ++j)
            a[j] = sqrtf(fmaf(v[j].x, v[j].x, v[j].y * v[j].y));
        #pragma unroll
        for (int j = 0; j < U_; ++j) {
            s = fmaf(ALPHA, s, ONE_MA * a[j]);
            float inv = rsqrtf(s + EPS_);
            float2 o;
            o.x = v[j].x * inv;
            o.y = v[j].y * inv;
            out[idx + j * F_] = o;
        }
        idx += U_ * F_;
    }
}

extern "C" void kernel_launch(void* const* d_in, const int* in_sizes, int n_in,
                              void* d_out, int out_size) {
    const float2* x = (const float2*)d_in[0];
    float2*     out = (float2*)d_out;
    int n = B_ * F_ * C_;               // 153,920 threads
    int threads = 256;
    int blocks = (n + threads - 1) / threads;
    specnorm_kernel<<<blocks, threads>>>(x, out);
}